// round 17
// baseline (speedup 1.0000x reference)
#include <cuda_runtime.h>
#include <cuda_fp16.h>
#include <cstdint>

#define B_  2
#define C_  256
#define H_  128
#define W_  128
#define HW_ (H_ * W_)
#define NH  32
#define NW  32

// ---------------------------------------------------------------------------
// Static scratch (no runtime allocation allowed).
// ---------------------------------------------------------------------------
__device__ __align__(256) __half g_Wh[3][C_ * C_];                // fp16(W), [O][K]
__device__ __align__(256) __half g_QKV[3][(size_t)B_ * C_ * HW_]; // Q,K,V fp16 [b][c][hw]

// ---------------------------------------------------------------------------
// Helpers
// ---------------------------------------------------------------------------
__device__ __forceinline__ uint32_t smem_u32(const void* p) {
  uint32_t a;
  asm("{ .reg .u64 t; cvta.to.shared.u64 t, %1; cvt.u32.u64 %0, t; }" : "=r"(a) : "l"(p));
  return a;
}

#define CP_ASYNC16(s, g) \
  asm volatile("cp.async.cg.shared.global [%0], [%1], 16;" :: "r"(s), "l"(g))
#define CP_COMMIT() asm volatile("cp.async.commit_group;" ::: "memory")
#define CP_WAIT0()  asm volatile("cp.async.wait_group 0;" ::: "memory")
#define CP_WAIT1()  asm volatile("cp.async.wait_group 1;" ::: "memory")

__device__ __forceinline__ void ldsm_x4(uint32_t* r, uint32_t addr) {
  asm volatile("ldmatrix.sync.aligned.m8n8.x4.shared.b16 {%0,%1,%2,%3}, [%4];"
               : "=r"(r[0]), "=r"(r[1]), "=r"(r[2]), "=r"(r[3]) : "r"(addr));
}
__device__ __forceinline__ void ldsm_x4_t(uint32_t* r, uint32_t addr) {
  asm volatile("ldmatrix.sync.aligned.m8n8.x4.trans.shared.b16 {%0,%1,%2,%3}, [%4];"
               : "=r"(r[0]), "=r"(r[1]), "=r"(r[2]), "=r"(r[3]) : "r"(addr));
}

__device__ __forceinline__ void mma_f16(float* c, const uint32_t* a, const uint32_t* b) {
  asm volatile(
      "mma.sync.aligned.m16n8k16.row.col.f32.f16.f16.f32 "
      "{%0,%1,%2,%3}, {%4,%5,%6,%7}, {%8,%9}, {%0,%1,%2,%3};"
      : "+f"(c[0]), "+f"(c[1]), "+f"(c[2]), "+f"(c[3])
      : "r"(a[0]), "r"(a[1]), "r"(a[2]), "r"(a[3]), "r"(b[0]), "r"(b[1]));
}

// A smem tile: 128 rows x 32 fp16 (64B rows, 4 x 16B chunks, XOR swizzle)
__device__ __forceinline__ uint32_t soff(int r, int c) {
  return (uint32_t)(r * 64 + ((c ^ ((r >> 1) & 3)) << 4));
}
// B smem tile: 32 k-rows x 128 n fp16 (256B rows, 16 x 16B chunks, XOR swizzle)
__device__ __forceinline__ uint32_t boff(int r, int c) {
  return (uint32_t)(r * 256 + ((c ^ (r & 7)) << 4));
}

// ---------------------------------------------------------------------------
// Kernel 0: weights -> fp16 (vectorized, 8 elems/thread).
// ---------------------------------------------------------------------------
__global__ void __launch_bounds__(256) convert_w_kernel(
    const float* __restrict__ qw, const float* __restrict__ kw,
    const float* __restrict__ vw) {
  int e = (blockIdx.x * 256 + threadIdx.x) * 8;
  int p = e >> 16;
  int r = e & 0xFFFF;
  const float* w = ((p == 0) ? qw : (p == 1) ? kw : vw) + r;
  float4 f0 = *(const float4*)w;
  float4 f1 = *(const float4*)(w + 4);
  __half2 h[4];
  h[0] = __floats2half2_rn(f0.x, f0.y);
  h[1] = __floats2half2_rn(f0.z, f0.w);
  h[2] = __floats2half2_rn(f1.x, f1.y);
  h[3] = __floats2half2_rn(f1.z, f1.w);
  *(uint4*)(g_Wh[p] + r) = *(uint4*)h;
}

// ---------------------------------------------------------------------------
// Kernel 1: single-pass fp16 GEMM via mma.sync (HMMA)  [R12, unchanged math].
// One batch per launch (b passed as arg); z = projection p only.
// ---------------------------------------------------------------------------
__global__ void __launch_bounds__(256, 2) gemm_mma_kernel(
    const float* __restrict__ blue, const float* __restrict__ white,
    const float* __restrict__ qb, const float* __restrict__ kb,
    const float* __restrict__ vb, int b) {
  extern __shared__ char sm[];
  const uint32_t sbase = smem_u32(sm);

  const int tid = threadIdx.x;
  const int lane = tid & 31;
  const int wid = tid >> 5;
  const int wm = wid >> 2;
  const int wn = wid & 3;

  const int p = blockIdx.z;         // 0..2
  const int m0 = blockIdx.y * 128;
  const int n0 = blockIdx.x * 128;

  const __half* __restrict__ gA = g_Wh[p] + m0 * C_;
  const float* __restrict__ Xsrc =
      ((p == 0) ? blue : white) + (size_t)b * C_ * HW_ + n0;

  const int stg_ar = tid >> 2;
  const int stg_ac = tid & 3;
  const int stg_br = tid >> 4;
  const int stg_bc = tid & 15;

  float acc[4][4][4];
#pragma unroll
  for (int mt = 0; mt < 4; mt++)
#pragma unroll
    for (int nt = 0; nt < 4; nt++)
#pragma unroll
      for (int e = 0; e < 4; e++) acc[mt][nt][e] = 0.f;

  float4 bf[2][2];

#define ISSUE_A(ks, buf)                                                        \
  {                                                                             \
    const int k0 = (ks) * 32;                                                   \
    _Pragma("unroll")                                                           \
    for (int it = 0; it < 2; it++) {                                            \
      int r = stg_ar + it * 64;                                                 \
      CP_ASYNC16(sbase + (buf) * 16384 + soff(r, stg_ac),                       \
                 gA + r * C_ + k0 + stg_ac * 8);                                \
    }                                                                           \
    CP_COMMIT();                                                                \
  }

#define LDG_B(ks)                                                               \
  {                                                                             \
    const float* bp = Xsrc + (size_t)((ks) * 32) * HW_;                         \
    _Pragma("unroll")                                                           \
    for (int it = 0; it < 2; it++) {                                            \
      const float* q = bp + (size_t)(stg_br + it * 16) * HW_ + stg_bc * 8;      \
      bf[it][0] = *(const float4*)q;                                            \
      bf[it][1] = *(const float4*)(q + 4);                                      \
    }                                                                           \
  }

#define STS_B(buf)                                                              \
  {                                                                             \
    _Pragma("unroll")                                                           \
    for (int it = 0; it < 2; it++) {                                            \
      int r = stg_br + it * 16;                                                 \
      __half2 h[4];                                                             \
      h[0] = __floats2half2_rn(bf[it][0].x, bf[it][0].y);                       \
      h[1] = __floats2half2_rn(bf[it][0].z, bf[it][0].w);                       \
      h[2] = __floats2half2_rn(bf[it][1].x, bf[it][1].y);                       \
      h[3] = __floats2half2_rn(bf[it][1].z, bf[it][1].w);                       \
      *(uint4*)(sm + (buf) * 16384 + 8192 + boff(r, stg_bc)) = *(uint4*)h;      \
    }                                                                           \
  }

  ISSUE_A(0, 0);
  LDG_B(0);

  for (int ks = 0; ks < 8; ks++) {
    const int buf = ks & 1;
    STS_B(buf);
    if (ks + 1 < 8) {
      LDG_B(ks + 1);
      ISSUE_A(ks + 1, buf ^ 1);
      CP_WAIT1();
    } else {
      CP_WAIT0();
    }
    __syncthreads();

    const uint32_t Ab = sbase + buf * 16384;
    const uint32_t Bb = Ab + 8192;

#pragma unroll
    for (int kc = 0; kc < 2; kc++) {
      uint32_t ah[4][4], bh[2][4];
      const int arow = wm * 64 + (lane & 15);
      const int achunk = kc * 2 + (lane >> 4);
#pragma unroll
      for (int mt = 0; mt < 4; mt++) {
        int rr = arow + mt * 16;
        ldsm_x4(ah[mt], Ab + soff(rr, achunk));
      }
      const int brow = kc * 16 + ((lane >> 3) & 1) * 8 + (lane & 7);
#pragma unroll
      for (int bt = 0; bt < 2; bt++) {
        int cb = wn * 4 + bt * 2 + (lane >> 4);
        ldsm_x4_t(bh[bt], Bb + boff(brow, cb));
      }
#pragma unroll
      for (int mt = 0; mt < 4; mt++) {
#pragma unroll
        for (int nt = 0; nt < 4; nt++) {
          mma_f16(acc[mt][nt], ah[mt], &bh[nt >> 1][(nt & 1) * 2]);
        }
      }
    }
    __syncthreads();
  }

  const float* __restrict__ biasp = (p == 0) ? qb : (p == 1) ? kb : vb;
  __half* __restrict__ Out = g_QKV[p] + (size_t)b * C_ * HW_;
  const int mrow_base = m0 + wm * 64 + (lane >> 2);
  const int ncol_base = n0 + wn * 32 + (lane & 3) * 2;

#pragma unroll
  for (int mt = 0; mt < 4; mt++) {
    int mr = mrow_base + mt * 16;
    float bi0 = __ldg(biasp + mr);
    float bi1 = __ldg(biasp + mr + 8);
#pragma unroll
    for (int nt = 0; nt < 4; nt++) {
      int nc = ncol_base + nt * 8;
      *(__half2*)(Out + (size_t)mr * HW_ + nc) =
          __floats2half2_rn(acc[mt][nt][0] + bi0, acc[mt][nt][1] + bi0);
      *(__half2*)(Out + (size_t)(mr + 8) * HW_ + nc) =
          __floats2half2_rn(acc[mt][nt][2] + bi1, acc[mt][nt][3] + bi1);
    }
  }
}

// ---------------------------------------------------------------------------
// Kernel 2: per-channel 3x3-neighbor token attention [R12, unchanged math].
// One batch per launch (b passed as arg).
// ---------------------------------------------------------------------------
__global__ void __launch_bounds__(256) attn_kernel(float* __restrict__ out, int b) {
  const int j = threadIdx.x;
  const int i = blockIdx.x;
  const int c = blockIdx.y * 8 + threadIdx.y;

  const size_t base = ((size_t)b * C_ + c) * HW_;
  const __half* __restrict__ Qp = g_QKV[0] + base;
  const __half* __restrict__ Kp = g_QKV[1] + base;
  const __half* __restrict__ Vp = g_QKV[2] + base;

  const int tok = (i * 4) * W_ + j * 4;

  __half2 qh[4][2];
#pragma unroll
  for (int r = 0; r < 4; r++) {
    uint2 u = *(const uint2*)(Qp + tok + r * W_);
    qh[r][0] = *(__half2*)&u.x;
    qh[r][1] = *(__half2*)&u.y;
  }

  float wsum = 0.f;
  float4 o0 = {0, 0, 0, 0}, o1 = {0, 0, 0, 0}, o2 = {0, 0, 0, 0}, o3 = {0, 0, 0, 0};

#pragma unroll
  for (int n = 0; n < 9; n++) {
    const int ii = i + n / 3 - 1;
    const int jj = j + n % 3 - 1;
    if ((unsigned)ii < (unsigned)NH && (unsigned)jj < (unsigned)NW) {
      const int noff = (ii * 4) * W_ + jj * 4;
      const __half* kp = Kp + noff;
      const __half* vp = Vp + noff;
      uint2 k0 = *(const uint2*)(kp);
      uint2 k1 = *(const uint2*)(kp + W_);
      uint2 k2 = *(const uint2*)(kp + 2 * W_);
      uint2 k3 = *(const uint2*)(kp + 3 * W_);
      uint2 v0 = *(const uint2*)(vp);
      uint2 v1 = *(const uint2*)(vp + W_);
      uint2 v2 = *(const uint2*)(vp + 2 * W_);
      uint2 v3 = *(const uint2*)(vp + 3 * W_);

      __half2 acc = __float2half2_rn(0.f);
      acc = __hfma2(qh[0][0], *(__half2*)&k0.x, acc);
      acc = __hfma2(qh[0][1], *(__half2*)&k0.y, acc);
      acc = __hfma2(qh[1][0], *(__half2*)&k1.x, acc);
      acc = __hfma2(qh[1][1], *(__half2*)&k1.y, acc);
      acc = __hfma2(qh[2][0], *(__half2*)&k2.x, acc);
      acc = __hfma2(qh[2][1], *(__half2*)&k2.y, acc);
      acc = __hfma2(qh[3][0], *(__half2*)&k3.x, acc);
      acc = __hfma2(qh[3][1], *(__half2*)&k3.y, acc);
      const float e = __expf((__low2float(acc) + __high2float(acc)) * 0.25f);
      wsum += e;

      float2 f;
      f = __half22float2(*(__half2*)&v0.x); o0.x = fmaf(e, f.x, o0.x); o0.y = fmaf(e, f.y, o0.y);
      f = __half22float2(*(__half2*)&v0.y); o0.z = fmaf(e, f.x, o0.z); o0.w = fmaf(e, f.y, o0.w);
      f = __half22float2(*(__half2*)&v1.x); o1.x = fmaf(e, f.x, o1.x); o1.y = fmaf(e, f.y, o1.y);
      f = __half22float2(*(__half2*)&v1.y); o1.z = fmaf(e, f.x, o1.z); o1.w = fmaf(e, f.y, o1.w);
      f = __half22float2(*(__half2*)&v2.x); o2.x = fmaf(e, f.x, o2.x); o2.y = fmaf(e, f.y, o2.y);
      f = __half22float2(*(__half2*)&v2.y); o2.z = fmaf(e, f.x, o2.z); o2.w = fmaf(e, f.y, o2.w);
      f = __half22float2(*(__half2*)&v3.x); o3.x = fmaf(e, f.x, o3.x); o3.y = fmaf(e, f.y, o3.y);
      f = __half22float2(*(__half2*)&v3.y); o3.z = fmaf(e, f.x, o3.z); o3.w = fmaf(e, f.y, o3.w);
    }
  }

  const float inv = 1.f / wsum;
  o0.x *= inv; o0.y *= inv; o0.z *= inv; o0.w *= inv;
  o1.x *= inv; o1.y *= inv; o1.z *= inv; o1.w *= inv;
  o2.x *= inv; o2.y *= inv; o2.z *= inv; o2.w *= inv;
  o3.x *= inv; o3.y *= inv; o3.z *= inv; o3.w *= inv;

  float* op = out + base + tok;
  *(float4*)(op)          = o0;
  *(float4*)(op + W_)     = o1;
  *(float4*)(op + 2 * W_) = o2;
  *(float4*)(op + 3 * W_) = o3;
}

// ---------------------------------------------------------------------------
// Launch: fork-join two-stream schedule so attn(b0) overlaps gemm(b1).
//   s0: convert_w -> gemm(b0) -> [evA] -> gemm(b1) -> attn(b1) -> wait(evB)
//   s1:                     wait(evA) -> attn(b0) -> [evB]
// Streams/events created once (host resources, no device allocation).
// ---------------------------------------------------------------------------
extern "C" void kernel_launch(void* const* d_in, const int* in_sizes, int n_in,
                              void* d_out, int out_size) {
  const float* blue  = (const float*)d_in[0];
  const float* white = (const float*)d_in[1];
  const float* qw    = (const float*)d_in[2];
  const float* qb    = (const float*)d_in[3];
  const float* kw    = (const float*)d_in[4];
  const float* kb    = (const float*)d_in[5];
  const float* vw    = (const float*)d_in[6];
  const float* vb    = (const float*)d_in[7];

  static cudaStream_t s1 = nullptr;
  static cudaEvent_t evA = nullptr, evB = nullptr;
  if (s1 == nullptr) {
    cudaStreamCreateWithFlags(&s1, cudaStreamNonBlocking);
    cudaEventCreateWithFlags(&evA, cudaEventDisableTiming);
    cudaEventCreateWithFlags(&evB, cudaEventDisableTiming);
    cudaFuncSetAttribute(gemm_mma_kernel,
                         cudaFuncAttributeMaxDynamicSharedMemorySize, 32768);
  }

  const dim3 ggrid(HW_ / 128, C_ / 128, 3);
  const dim3 agrid(NH, C_ / 8, 1);
  const dim3 ablk(32, 8);
  float* out = (float*)d_out;

  convert_w_kernel<<<(3 * C_ * C_) / (256 * 8), 256>>>(qw, kw, vw);
  gemm_mma_kernel<<<ggrid, 256, 32768>>>(blue, white, qb, kb, vb, 0);
  cudaEventRecord(evA, 0);                    // after gemm(b0) on main stream

  cudaStreamWaitEvent(s1, evA, 0);            // fork
  attn_kernel<<<agrid, ablk, 0, s1>>>(out, 0);
  cudaEventRecord(evB, s1);

  gemm_mma_kernel<<<ggrid, 256, 32768>>>(blue, white, qb, kb, vb, 1);
  attn_kernel<<<agrid, ablk>>>(out, 1);
  cudaStreamWaitEvent(0, evB, 0);             // join
}